// round 9
// baseline (speedup 1.0000x reference)
#include <cuda_runtime.h>
#include <cuda_bf16.h>
#include <cstdint>
#include <cstddef>

// O3 tensor product, MUL=64, via mma.sync bf16 (hi/lo split, fp32 accum).
//   Q1 = s1 @ Wss ; Q2 = b @ Wvv ; P3 = s1 @ Wsv ; P4i = v1_i @ Wvs
//   out_s       = s2*Q1 + Q2 + bias
//   out_v[w][i] = P3[w]*v2_i + P4i[w]*s2
// (all reference scale factors cancel; b = dot(v1,v2)/sqrt(3))
//
// R9: MMA issue order interleaved across independent accumulators — no two
// consecutive HMMAs share an accumulator (breaks 3-deep RAW chains that were
// capping tensor pipe at 36%).

#define THREADS 512
#define RPC 32                      // rows per chunk
#define MAT_BYTES (RPC * 128)       // one staged A matrix: 32 rows x 128B (64 bf16)
#define BUF_BYTES (10 * MAT_BYTES + 512)
#define SMEM_BYTES (2 * BUF_BYTES)

typedef unsigned int u32;

__device__ __forceinline__ u32 smem_u32(const void* p) {
    u32 a; asm("{ .reg .u64 t; cvta.to.shared.u64 t, %1; cvt.u32.u64 %0, t; }" : "=r"(a) : "l"(p));
    return a;
}

__device__ __forceinline__ void ldsm4(u32* d, u32 addr) {
    asm volatile("ldmatrix.sync.aligned.m8n8.x4.shared.b16 {%0,%1,%2,%3}, [%4];"
                 : "=r"(d[0]), "=r"(d[1]), "=r"(d[2]), "=r"(d[3]) : "r"(addr));
}

__device__ __forceinline__ void mma16816(float* c, const u32* a, const u32* b) {
    asm volatile("mma.sync.aligned.m16n8k16.row.col.f32.bf16.bf16.f32 "
                 "{%0,%1,%2,%3},{%4,%5,%6,%7},{%8,%9},{%0,%1,%2,%3};"
                 : "+f"(c[0]), "+f"(c[1]), "+f"(c[2]), "+f"(c[3])
                 : "r"(a[0]), "r"(a[1]), "r"(a[2]), "r"(a[3]), "r"(b[0]), "r"(b[1]));
}

// split two floats into packed bf16x2 hi and lo (lo = residual)
__device__ __forceinline__ void split2(float x0, float x1, u32& hi, u32& lo) {
    __nv_bfloat162 h = __floats2bfloat162_rn(x0, x1);
    float r0 = x0 - __bfloat162float(h.x);
    float r1 = x1 - __bfloat162float(h.y);
    __nv_bfloat162 l = __floats2bfloat162_rn(r0, r1);
    hi = *(u32*)&h; lo = *(u32*)&l;
}

// pack 4 floats -> hi uint2 + lo uint2 (bf16)
__device__ __forceinline__ void pack4(const float* x, uint2& hi, uint2& lo) {
    u32 h0, h1, l0, l1;
    split2(x[0], x[1], h0, l0);
    split2(x[2], x[3], h1, l1);
    hi = make_uint2(h0, h1);
    lo = make_uint2(l0, l1);
}

// Per-thread staged registers for one chunk work-item:
// r = t>>4 (row 0..31), g4 = t&15 (u-group of 4: u = 4g4..4g4+3)
struct ChunkRegs {
    float4 s1a;
    float4 v0, v1, v2;
    float4 q;
};

__device__ __forceinline__ void chunk_load(ChunkRegs& cr, const float* __restrict__ in1,
                                           const float* __restrict__ in2,
                                           int row0, int n, int t)
{
    const int r = t >> 4, g4 = t & 15;
    int row = row0 + r; if (row >= n) row = n - 1;
    const float4* p1 = (const float4*)(in1 + (size_t)row * 256);
    cr.s1a = p1[g4];
    cr.v0  = p1[16 + 3 * g4];
    cr.v1  = p1[16 + 3 * g4 + 1];
    cr.v2  = p1[16 + 3 * g4 + 2];
    cr.q   = *(const float4*)(in2 + (size_t)row * 4);
}

// A-matrix order in staging: 0 s1h 1 s1l 2 bh 3 bl 4 xh 5 xl 6 yh 7 yl 8 zh 9 zl
__device__ __forceinline__ void chunk_store(char* buf, const ChunkRegs& cr, int t)
{
    const int r = t >> 4, g4 = t & 15;
    if (g4 == 0) *(float4*)(buf + 10 * MAT_BYTES + r * 16) = cr.q;

    const float s1[4] = { cr.s1a.x, cr.s1a.y, cr.s1a.z, cr.s1a.w };
    const float vv[12] = { cr.v0.x, cr.v0.y, cr.v0.z, cr.v0.w,
                           cr.v1.x, cr.v1.y, cr.v1.z, cr.v1.w,
                           cr.v2.x, cr.v2.y, cr.v2.z, cr.v2.w };
    const float INV_SQRT3 = 0.57735026918962576451f;
    float bb[4], vx[4], vy[4], vz[4];
#pragma unroll
    for (int j = 0; j < 4; j++) {
        vx[j] = vv[3 * j]; vy[j] = vv[3 * j + 1]; vz[j] = vv[3 * j + 2];
        bb[j] = (vx[j] * cr.q.y + vy[j] * cr.q.z + vz[j] * cr.q.w) * INV_SQRT3;
    }

    const u32 off = (u32)(r * 128 + (((g4 >> 1) ^ (r & 7)) << 4) + (g4 & 1) * 8);
    uint2 hi, lo;
    pack4(s1, hi, lo);
    *(uint2*)(buf + 0 * MAT_BYTES + off) = hi; *(uint2*)(buf + 1 * MAT_BYTES + off) = lo;
    pack4(bb, hi, lo);
    *(uint2*)(buf + 2 * MAT_BYTES + off) = hi; *(uint2*)(buf + 3 * MAT_BYTES + off) = lo;
    pack4(vx, hi, lo);
    *(uint2*)(buf + 4 * MAT_BYTES + off) = hi; *(uint2*)(buf + 5 * MAT_BYTES + off) = lo;
    pack4(vy, hi, lo);
    *(uint2*)(buf + 6 * MAT_BYTES + off) = hi; *(uint2*)(buf + 7 * MAT_BYTES + off) = lo;
    pack4(vz, hi, lo);
    *(uint2*)(buf + 8 * MAT_BYTES + off) = hi; *(uint2*)(buf + 9 * MAT_BYTES + off) = lo;
}

__global__ void __launch_bounds__(THREADS, 1)
o3tp_mma_kernel(const float* __restrict__ in1, const float* __restrict__ in2,
                const float* __restrict__ Wss, const float* __restrict__ Wvv,
                const float* __restrict__ Wsv, const float* __restrict__ Wvs,
                const float* __restrict__ bias, float* __restrict__ out, int n)
{
    extern __shared__ char smem[];
    const u32 sbase = smem_u32(smem);
    const int t = threadIdx.x, wid = t >> 5, lane = t & 31;
    const int nw = wid & 7;         // n-slice: cols nw*8..nw*8+7
    const int mt = wid >> 3;        // m-half: rows mt*16..mt*16+15

    // ---- persistent B fragments: warp's n-slice (8 cols) of all 4 matrices ----
    u32 Bh[4][4][2], Bl[4][4][2];
    {
        const int wcol = nw * 8 + (lane >> 2);
        const float* Ws[4] = { Wss, Wvv, Wsv, Wvs };
#pragma unroll
        for (int m = 0; m < 4; m++)
#pragma unroll
            for (int kt = 0; kt < 4; kt++)
#pragma unroll
                for (int b2 = 0; b2 < 2; b2++) {
                    const int u = kt * 16 + (lane & 3) * 2 + b2 * 8;
                    const float w0 = __ldg(Ws[m] + u * 64 + wcol);
                    const float w1 = __ldg(Ws[m] + (u + 1) * 64 + wcol);
                    split2(w0, w1, Bh[m][kt][b2], Bl[m][kt][b2]);
                }
    }
    float2 bias2;
    {
        const int w0 = nw * 8 + (lane & 3) * 2;
        bias2 = make_float2(__ldg(bias + w0), __ldg(bias + w0 + 1));
    }

    const int nch = (n + RPC - 1) / RPC;
    int c = blockIdx.x;
    ChunkRegs cr;
    if (c < nch) {
        chunk_load(cr, in1, in2, c * RPC, n, t);
        chunk_store(smem, cr, t);
    }
    __syncthreads();

    int p = 0;
    for (; c < nch; c += gridDim.x) {
        const int cn = c + gridDim.x;
        const bool have_next = cn < nch;
        if (have_next) chunk_load(cr, in1, in2, cn * RPC, n, t);

        // ---- MMA phase on buffer p: warp computes M=16 (m-half mt), N=8 (nw) ----
        float acc[6][4];
#pragma unroll
        for (int g = 0; g < 6; g++)
#pragma unroll
            for (int k = 0; k < 4; k++) acc[g][k] = 0.0f;

        const u32 abase = sbase + (u32)(p * BUF_BYTES);
        const int rl = lane & 15;
        const int rlo = rl & 7;
        const int rr = mt * 16 + rl;
#pragma unroll
        for (int kt = 0; kt < 4; kt++) {
            const int cb = (kt * 2 + (lane >> 4)) ^ rlo;
            const u32 aoff = abase + (u32)(rr * 128 + cb * 16);

            // group 1: s1 (-> Wss:acc0, Wsv:acc2) and b (-> Wvv:acc1)
            u32 sh_[4], sl_[4], bh_[4], bl_[4];
            ldsm4(sh_, aoff + 0 * MAT_BYTES);
            ldsm4(sl_, aoff + 1 * MAT_BYTES);
            ldsm4(bh_, aoff + 2 * MAT_BYTES);
            ldsm4(bl_, aoff + 3 * MAT_BYTES);
            // round-robin accs: acc0, acc2, acc1, acc0, acc2, acc1, ...
            mma16816(acc[0], sh_, Bh[0][kt]);
            mma16816(acc[2], sh_, Bh[2][kt]);
            mma16816(acc[1], bh_, Bh[1][kt]);
            mma16816(acc[0], sl_, Bh[0][kt]);
            mma16816(acc[2], sl_, Bh[2][kt]);
            mma16816(acc[1], bl_, Bh[1][kt]);
            mma16816(acc[0], sh_, Bl[0][kt]);
            mma16816(acc[2], sh_, Bl[2][kt]);
            mma16816(acc[1], bh_, Bl[1][kt]);

            // group 2: vx, vy, vz -> Wvs (acc3, acc4, acc5)
            u32 xh_[4], xl_[4], yh_[4], yl_[4], zh_[4], zl_[4];
            ldsm4(xh_, aoff + 4 * MAT_BYTES);
            ldsm4(xl_, aoff + 5 * MAT_BYTES);
            ldsm4(yh_, aoff + 6 * MAT_BYTES);
            ldsm4(yl_, aoff + 7 * MAT_BYTES);
            ldsm4(zh_, aoff + 8 * MAT_BYTES);
            ldsm4(zl_, aoff + 9 * MAT_BYTES);
            mma16816(acc[3], xh_, Bh[3][kt]);
            mma16816(acc[4], yh_, Bh[3][kt]);
            mma16816(acc[5], zh_, Bh[3][kt]);
            mma16816(acc[3], xl_, Bh[3][kt]);
            mma16816(acc[4], yl_, Bh[3][kt]);
            mma16816(acc[5], zl_, Bh[3][kt]);
            mma16816(acc[3], xh_, Bl[3][kt]);
            mma16816(acc[4], yh_, Bl[3][kt]);
            mma16816(acc[5], zh_, Bl[3][kt]);
        }

        // ---- epilogue ----
        const float4* sin2 = (const float4*)(smem + p * BUF_BYTES + 10 * MAT_BYTES);
        const int row0 = c * RPC;
        const int wc = nw * 8 + (lane & 3) * 2;
#pragma unroll
        for (int h = 0; h < 2; h++) {
            const int rloc = mt * 16 + (lane >> 2) + h * 8;
            const int row = row0 + rloc;
            if (row >= n) continue;
            const float4 q = sin2[rloc];
            float* o = out + (size_t)row * 256;
            const int ci = h * 2;
            const float s0  = q.x * acc[0][ci]     + acc[1][ci]     + bias2.x;
            const float s1v = q.x * acc[0][ci + 1] + acc[1][ci + 1] + bias2.y;
            *(float2*)(o + wc) = make_float2(s0, s1v);

            float vv6[6];
#pragma unroll
            for (int j = 0; j < 2; j++) {
                const float p3 = acc[2][ci + j];
                vv6[3 * j]     = p3 * q.y + acc[3][ci + j] * q.x;
                vv6[3 * j + 1] = p3 * q.z + acc[4][ci + j] * q.x;
                vv6[3 * j + 2] = p3 * q.w + acc[5][ci + j] * q.x;
            }
            float* ov = o + 64 + 3 * wc;
            *(float2*)(ov)     = make_float2(vv6[0], vv6[1]);
            *(float2*)(ov + 2) = make_float2(vv6[2], vv6[3]);
            *(float2*)(ov + 4) = make_float2(vv6[4], vv6[5]);
        }

        // ---- pack + store next chunk (loads have landed by now) ----
        if (have_next) chunk_store(smem + (p ^ 1) * BUF_BYTES, cr, t);

        __syncthreads();
        p ^= 1;
    }
}

extern "C" void kernel_launch(void* const* d_in, const int* in_sizes, int n_in,
                              void* d_out, int out_size)
{
    const float* in1  = (const float*)d_in[0];
    const float* in2  = (const float*)d_in[1];
    const float* Wss  = (const float*)d_in[2];
    const float* Wvv  = (const float*)d_in[3];
    const float* Wsv  = (const float*)d_in[4];
    const float* Wvs  = (const float*)d_in[5];
    const float* bias = (const float*)d_in[6];
    float* out = (float*)d_out;

    const int n = in_sizes[0] / 256;

    cudaFuncSetAttribute(o3tp_mma_kernel, cudaFuncAttributeMaxDynamicSharedMemorySize, SMEM_BYTES);

    int dev = 0, sms = 148;
    cudaGetDevice(&dev);
    cudaDeviceGetAttribute(&sms, cudaDevAttrMultiProcessorCount, dev);

    o3tp_mma_kernel<<<sms, THREADS, SMEM_BYTES>>>(in1, in2, Wss, Wvv, Wsv, Wvs, bias, out, n);
}

// round 10
// speedup vs baseline: 1.3229x; 1.3229x over previous
#include <cuda_runtime.h>
#include <cuda_fp16.h>
#include <cstdint>
#include <cstddef>

// O3 tensor product, MUL=64, via mma.sync fp16 (A single-precision fp16,
// B = weights split hi+lo fp16 in registers, fp32 accum).
//   Q1 = s1 @ Wss ; Q2 = b @ Wvv ; P3 = s1 @ Wsv ; P4i = v1_i @ Wvs
//   out_s       = s2*Q1 + Q2 + bias
//   out_v[w][i] = P3[w]*v2_i + P4i[w]*s2
// (all reference scale factors cancel; b = dot(v1,v2)/sqrt(3))
//
// R10: A matrices stored hi-only fp16 -> 5 staged matrices instead of 10;
// ldsm traffic (the measured limiter, 8x duplicated across n-slice warps)
// halves; MMA count drops 72 -> 48 per warp.

#define THREADS 512
#define RPC 32                      // rows per chunk
#define MAT_BYTES (RPC * 128)       // one staged A matrix: 32 rows x 128B (64 fp16)
#define NMAT 5                      // s1, b, vx, vy, vz
#define BUF_BYTES (NMAT * MAT_BYTES + 512)
#define SMEM_BYTES (2 * BUF_BYTES)

typedef unsigned int u32;

__device__ __forceinline__ u32 smem_u32(const void* p) {
    u32 a; asm("{ .reg .u64 t; cvta.to.shared.u64 t, %1; cvt.u32.u64 %0, t; }" : "=r"(a) : "l"(p));
    return a;
}

__device__ __forceinline__ void ldsm4(u32* d, u32 addr) {
    asm volatile("ldmatrix.sync.aligned.m8n8.x4.shared.b16 {%0,%1,%2,%3}, [%4];"
                 : "=r"(d[0]), "=r"(d[1]), "=r"(d[2]), "=r"(d[3]) : "r"(addr));
}

__device__ __forceinline__ void mma16816(float* c, const u32* a, const u32* b) {
    asm volatile("mma.sync.aligned.m16n8k16.row.col.f32.f16.f16.f32 "
                 "{%0,%1,%2,%3},{%4,%5,%6,%7},{%8,%9},{%0,%1,%2,%3};"
                 : "+f"(c[0]), "+f"(c[1]), "+f"(c[2]), "+f"(c[3])
                 : "r"(a[0]), "r"(a[1]), "r"(a[2]), "r"(a[3]), "r"(b[0]), "r"(b[1]));
}

// split two floats into packed fp16x2 hi and lo (lo = residual)
__device__ __forceinline__ void splitH2(float x0, float x1, u32& hi, u32& lo) {
    __half2 h = __floats2half2_rn(x0, x1);
    float r0 = x0 - __half2float(__low2half(h));
    float r1 = x1 - __half2float(__high2half(h));
    __half2 l = __floats2half2_rn(r0, r1);
    hi = *(u32*)&h; lo = *(u32*)&l;
}

// pack 4 floats -> 4 fp16 (uint2), round-to-nearest
__device__ __forceinline__ uint2 pack4h(const float* x) {
    __half2 a = __floats2half2_rn(x[0], x[1]);
    __half2 b = __floats2half2_rn(x[2], x[3]);
    return make_uint2(*(u32*)&a, *(u32*)&b);
}

// Per-thread staged registers for one chunk work-item:
// r = t>>4 (row 0..31), g4 = t&15 (u-group of 4: u = 4g4..4g4+3)
struct ChunkRegs {
    float4 s1a;
    float4 v0, v1, v2;
    float4 q;
};

__device__ __forceinline__ void chunk_load(ChunkRegs& cr, const float* __restrict__ in1,
                                           const float* __restrict__ in2,
                                           int row0, int n, int t)
{
    const int r = t >> 4, g4 = t & 15;
    int row = row0 + r; if (row >= n) row = n - 1;
    const float4* p1 = (const float4*)(in1 + (size_t)row * 256);
    cr.s1a = p1[g4];
    cr.v0  = p1[16 + 3 * g4];
    cr.v1  = p1[16 + 3 * g4 + 1];
    cr.v2  = p1[16 + 3 * g4 + 2];
    cr.q   = *(const float4*)(in2 + (size_t)row * 4);
}

// A-matrix order in staging: 0 s1, 1 b, 2 vx, 3 vy, 4 vz  (fp16, hi only)
__device__ __forceinline__ void chunk_store(char* buf, const ChunkRegs& cr, int t)
{
    const int r = t >> 4, g4 = t & 15;
    if (g4 == 0) *(float4*)(buf + NMAT * MAT_BYTES + r * 16) = cr.q;

    const float s1[4] = { cr.s1a.x, cr.s1a.y, cr.s1a.z, cr.s1a.w };
    const float vv[12] = { cr.v0.x, cr.v0.y, cr.v0.z, cr.v0.w,
                           cr.v1.x, cr.v1.y, cr.v1.z, cr.v1.w,
                           cr.v2.x, cr.v2.y, cr.v2.z, cr.v2.w };
    const float INV_SQRT3 = 0.57735026918962576451f;
    float bb[4], vx[4], vy[4], vz[4];
#pragma unroll
    for (int j = 0; j < 4; j++) {
        vx[j] = vv[3 * j]; vy[j] = vv[3 * j + 1]; vz[j] = vv[3 * j + 2];
        bb[j] = (vx[j] * cr.q.y + vy[j] * cr.q.z + vz[j] * cr.q.w) * INV_SQRT3;
    }

    // swizzled 8B offset: 16B block = g4>>1, XOR with row&7, sub-8B = g4&1
    const u32 off = (u32)(r * 128 + (((g4 >> 1) ^ (r & 7)) << 4) + (g4 & 1) * 8);
    *(uint2*)(buf + 0 * MAT_BYTES + off) = pack4h(s1);
    *(uint2*)(buf + 1 * MAT_BYTES + off) = pack4h(bb);
    *(uint2*)(buf + 2 * MAT_BYTES + off) = pack4h(vx);
    *(uint2*)(buf + 3 * MAT_BYTES + off) = pack4h(vy);
    *(uint2*)(buf + 4 * MAT_BYTES + off) = pack4h(vz);
}

__global__ void __launch_bounds__(THREADS, 1)
o3tp_mma_kernel(const float* __restrict__ in1, const float* __restrict__ in2,
                const float* __restrict__ Wss, const float* __restrict__ Wvv,
                const float* __restrict__ Wsv, const float* __restrict__ Wvs,
                const float* __restrict__ bias, float* __restrict__ out, int n)
{
    extern __shared__ char smem[];
    const u32 sbase = smem_u32(smem);
    const int t = threadIdx.x, wid = t >> 5, lane = t & 31;
    const int nw = wid & 7;         // n-slice: cols nw*8..nw*8+7
    const int mt = wid >> 3;        // m-half: rows mt*16..mt*16+15

    // ---- persistent B fragments: warp's n-slice (8 cols) of all 4 matrices,
    //      fp16 hi + lo (weights effectively exact) ----
    u32 Bh[4][4][2], Bl[4][4][2];
    {
        const int wcol = nw * 8 + (lane >> 2);
        const float* Ws[4] = { Wss, Wvv, Wsv, Wvs };
#pragma unroll
        for (int m = 0; m < 4; m++)
#pragma unroll
            for (int kt = 0; kt < 4; kt++)
#pragma unroll
                for (int b2 = 0; b2 < 2; b2++) {
                    const int u = kt * 16 + (lane & 3) * 2 + b2 * 8;
                    const float w0 = __ldg(Ws[m] + u * 64 + wcol);
                    const float w1 = __ldg(Ws[m] + (u + 1) * 64 + wcol);
                    splitH2(w0, w1, Bh[m][kt][b2], Bl[m][kt][b2]);
                }
    }
    float2 bias2;
    {
        const int w0 = nw * 8 + (lane & 3) * 2;
        bias2 = make_float2(__ldg(bias + w0), __ldg(bias + w0 + 1));
    }

    const int nch = (n + RPC - 1) / RPC;
    int c = blockIdx.x;
    ChunkRegs cr;
    if (c < nch) {
        chunk_load(cr, in1, in2, c * RPC, n, t);
        chunk_store(smem, cr, t);
    }
    __syncthreads();

    int p = 0;
    for (; c < nch; c += gridDim.x) {
        const int cn = c + gridDim.x;
        const bool have_next = cn < nch;
        if (have_next) chunk_load(cr, in1, in2, cn * RPC, n, t);

        // ---- MMA phase on buffer p: warp computes M=16 (m-half mt), N=8 (nw) ----
        float acc[6][4];
#pragma unroll
        for (int g = 0; g < 6; g++)
#pragma unroll
            for (int k = 0; k < 4; k++) acc[g][k] = 0.0f;

        const u32 abase = sbase + (u32)(p * BUF_BYTES);
        const int rl = lane & 15;
        const int rlo = rl & 7;
        const int rr = mt * 16 + rl;
#pragma unroll
        for (int kt = 0; kt < 4; kt++) {
            const int cb = (kt * 2 + (lane >> 4)) ^ rlo;
            const u32 aoff = abase + (u32)(rr * 128 + cb * 16);

            u32 sA[4], bA[4], xA[4], yA[4], zA[4];
            ldsm4(sA, aoff + 0 * MAT_BYTES);
            ldsm4(bA, aoff + 1 * MAT_BYTES);
            ldsm4(xA, aoff + 2 * MAT_BYTES);
            ldsm4(yA, aoff + 3 * MAT_BYTES);
            ldsm4(zA, aoff + 4 * MAT_BYTES);

            // 12 MMAs, round-robin across 6 independent accumulators
            mma16816(acc[0], sA, Bh[0][kt]);
            mma16816(acc[1], bA, Bh[1][kt]);
            mma16816(acc[2], sA, Bh[2][kt]);
            mma16816(acc[3], xA, Bh[3][kt]);
            mma16816(acc[4], yA, Bh[3][kt]);
            mma16816(acc[5], zA, Bh[3][kt]);
            mma16816(acc[0], sA, Bl[0][kt]);
            mma16816(acc[1], bA, Bl[1][kt]);
            mma16816(acc[2], sA, Bl[2][kt]);
            mma16816(acc[3], xA, Bl[3][kt]);
            mma16816(acc[4], yA, Bl[3][kt]);
            mma16816(acc[5], zA, Bl[3][kt]);
        }

        // ---- epilogue ----
        const float4* sin2 = (const float4*)(smem + p * BUF_BYTES + NMAT * MAT_BYTES);
        const int row0 = c * RPC;
        const int wc = nw * 8 + (lane & 3) * 2;
#pragma unroll
        for (int h = 0; h < 2; h++) {
            const int rloc = mt * 16 + (lane >> 2) + h * 8;
            const int row = row0 + rloc;
            if (row >= n) continue;
            const float4 q = sin2[rloc];
            float* o = out + (size_t)row * 256;
            const int ci = h * 2;
            const float s0  = q.x * acc[0][ci]     + acc[1][ci]     + bias2.x;
            const float s1v = q.x * acc[0][ci + 1] + acc[1][ci + 1] + bias2.y;
            *(float2*)(o + wc) = make_float2(s0, s1v);

            float vv6[6];
#pragma unroll
            for (int j = 0; j < 2; j++) {
                const float p3 = acc[2][ci + j];
                vv6[3 * j]     = p3 * q.y + acc[3][ci + j] * q.x;
                vv6[3 * j + 1] = p3 * q.z + acc[4][ci + j] * q.x;
                vv6[3 * j + 2] = p3 * q.w + acc[5][ci + j] * q.x;
            }
            float* ov = o + 64 + 3 * wc;
            *(float2*)(ov)     = make_float2(vv6[0], vv6[1]);
            *(float2*)(ov + 2) = make_float2(vv6[2], vv6[3]);
            *(float2*)(ov + 4) = make_float2(vv6[4], vv6[5]);
        }

        // ---- pack + store next chunk (loads have landed by now) ----
        if (have_next) chunk_store(smem + (p ^ 1) * BUF_BYTES, cr, t);

        __syncthreads();
        p ^= 1;
    }
}

extern "C" void kernel_launch(void* const* d_in, const int* in_sizes, int n_in,
                              void* d_out, int out_size)
{
    const float* in1  = (const float*)d_in[0];
    const float* in2  = (const float*)d_in[1];
    const float* Wss  = (const float*)d_in[2];
    const float* Wvv  = (const float*)d_in[3];
    const float* Wsv  = (const float*)d_in[4];
    const float* Wvs  = (const float*)d_in[5];
    const float* bias = (const float*)d_in[6];
    float* out = (float*)d_out;

    const int n = in_sizes[0] / 256;

    cudaFuncSetAttribute(o3tp_mma_kernel, cudaFuncAttributeMaxDynamicSharedMemorySize, SMEM_BYTES);

    int dev = 0, sms = 148;
    cudaGetDevice(&dev);
    cudaDeviceGetAttribute(&sms, cudaDevAttrMultiProcessorCount, dev);

    o3tp_mma_kernel<<<sms, THREADS, SMEM_BYTES>>>(in1, in2, Wss, Wvv, Wsv, Wvs, bias, out, n);
}

// round 11
// speedup vs baseline: 1.4646x; 1.1071x over previous
#include <cuda_runtime.h>
#include <cuda_fp16.h>
#include <cstdint>
#include <cstddef>

// O3 tensor product, MUL=64, via mma.sync fp16 (A single-precision fp16,
// B = weights split hi+lo fp16 in registers, fp32 accum).
//   Q1 = s1 @ Wss ; Q2 = b @ Wvv ; P3 = s1 @ Wsv ; P4i = v1_i @ Wvs
//   out_s       = s2*Q1 + Q2 + bias
//   out_v[w][i] = P3[w]*v2_i + P4i[w]*s2
// (all reference scale factors cancel; b = dot(v1,v2)/sqrt(3))
//
// R11: 2 CTAs/SM (256 threads each, RPC=16) — the two CTAs run out of phase,
// overlapping one CTA's MMA with the other's pack/epilogue/LDG. Per-row
// instruction counts identical to R10.

#define THREADS 256
#define RPC 16                      // rows per chunk (one m16 tile)
#define MAT_BYTES (RPC * 128)       // one staged A matrix: 16 rows x 128B (64 fp16)
#define NMAT 5                      // s1, b, vx, vy, vz
#define BUF_BYTES (NMAT * MAT_BYTES + 512)
#define SMEM_BYTES (2 * BUF_BYTES)

typedef unsigned int u32;

__device__ __forceinline__ u32 smem_u32(const void* p) {
    u32 a; asm("{ .reg .u64 t; cvta.to.shared.u64 t, %1; cvt.u32.u64 %0, t; }" : "=r"(a) : "l"(p));
    return a;
}

__device__ __forceinline__ void ldsm4(u32* d, u32 addr) {
    asm volatile("ldmatrix.sync.aligned.m8n8.x4.shared.b16 {%0,%1,%2,%3}, [%4];"
                 : "=r"(d[0]), "=r"(d[1]), "=r"(d[2]), "=r"(d[3]) : "r"(addr));
}

__device__ __forceinline__ void mma16816(float* c, const u32* a, const u32* b) {
    asm volatile("mma.sync.aligned.m16n8k16.row.col.f32.f16.f16.f32 "
                 "{%0,%1,%2,%3},{%4,%5,%6,%7},{%8,%9},{%0,%1,%2,%3};"
                 : "+f"(c[0]), "+f"(c[1]), "+f"(c[2]), "+f"(c[3])
                 : "r"(a[0]), "r"(a[1]), "r"(a[2]), "r"(a[3]), "r"(b[0]), "r"(b[1]));
}

// split two floats into packed fp16x2 hi and lo (lo = residual)
__device__ __forceinline__ void splitH2(float x0, float x1, u32& hi, u32& lo) {
    __half2 h = __floats2half2_rn(x0, x1);
    float r0 = x0 - __half2float(__low2half(h));
    float r1 = x1 - __half2float(__high2half(h));
    __half2 l = __floats2half2_rn(r0, r1);
    hi = *(u32*)&h; lo = *(u32*)&l;
}

// pack 4 floats -> 4 fp16 (uint2), round-to-nearest
__device__ __forceinline__ uint2 pack4h(const float* x) {
    __half2 a = __floats2half2_rn(x[0], x[1]);
    __half2 b = __floats2half2_rn(x[2], x[3]);
    return make_uint2(*(u32*)&a, *(u32*)&b);
}

// Per-thread staged registers for one chunk work-item:
// r = t>>4 (row 0..15), g4 = t&15 (u-group of 4: u = 4g4..4g4+3)
struct ChunkRegs {
    float4 s1a;
    float4 v0, v1, v2;
    float4 q;
};

__device__ __forceinline__ void chunk_load(ChunkRegs& cr, const float* __restrict__ in1,
                                           const float* __restrict__ in2,
                                           int row0, int n, int t)
{
    const int r = t >> 4, g4 = t & 15;
    int row = row0 + r; if (row >= n) row = n - 1;
    const float4* p1 = (const float4*)(in1 + (size_t)row * 256);
    cr.s1a = p1[g4];
    cr.v0  = p1[16 + 3 * g4];
    cr.v1  = p1[16 + 3 * g4 + 1];
    cr.v2  = p1[16 + 3 * g4 + 2];
    cr.q   = *(const float4*)(in2 + (size_t)row * 4);
}

// A-matrix order in staging: 0 s1, 1 b, 2 vx, 3 vy, 4 vz  (fp16, hi only)
__device__ __forceinline__ void chunk_store(char* buf, const ChunkRegs& cr, int t)
{
    const int r = t >> 4, g4 = t & 15;
    if (g4 == 0) *(float4*)(buf + NMAT * MAT_BYTES + r * 16) = cr.q;

    const float s1[4] = { cr.s1a.x, cr.s1a.y, cr.s1a.z, cr.s1a.w };
    const float vv[12] = { cr.v0.x, cr.v0.y, cr.v0.z, cr.v0.w,
                           cr.v1.x, cr.v1.y, cr.v1.z, cr.v1.w,
                           cr.v2.x, cr.v2.y, cr.v2.z, cr.v2.w };
    const float INV_SQRT3 = 0.57735026918962576451f;
    float bb[4], vx[4], vy[4], vz[4];
#pragma unroll
    for (int j = 0; j < 4; j++) {
        vx[j] = vv[3 * j]; vy[j] = vv[3 * j + 1]; vz[j] = vv[3 * j + 2];
        bb[j] = (vx[j] * cr.q.y + vy[j] * cr.q.z + vz[j] * cr.q.w) * INV_SQRT3;
    }

    // swizzled 8B offset: 16B block = g4>>1, XOR with row&7, sub-8B = g4&1
    const u32 off = (u32)(r * 128 + (((g4 >> 1) ^ (r & 7)) << 4) + (g4 & 1) * 8);
    *(uint2*)(buf + 0 * MAT_BYTES + off) = pack4h(s1);
    *(uint2*)(buf + 1 * MAT_BYTES + off) = pack4h(bb);
    *(uint2*)(buf + 2 * MAT_BYTES + off) = pack4h(vx);
    *(uint2*)(buf + 3 * MAT_BYTES + off) = pack4h(vy);
    *(uint2*)(buf + 4 * MAT_BYTES + off) = pack4h(vz);
}

__global__ void __launch_bounds__(THREADS, 2)
o3tp_mma_kernel(const float* __restrict__ in1, const float* __restrict__ in2,
                const float* __restrict__ Wss, const float* __restrict__ Wvv,
                const float* __restrict__ Wsv, const float* __restrict__ Wvs,
                const float* __restrict__ bias, float* __restrict__ out, int n)
{
    extern __shared__ char smem[];
    const u32 sbase = smem_u32(smem);
    const int t = threadIdx.x, wid = t >> 5, lane = t & 31;
    const int nw = wid;             // n-slice: cols nw*8..nw*8+7 (8 warps)

    // ---- persistent B fragments: warp's n-slice (8 cols) of all 4 matrices,
    //      fp16 hi + lo (weights effectively exact) ----
    u32 Bh[4][4][2], Bl[4][4][2];
    {
        const int wcol = nw * 8 + (lane >> 2);
        const float* Ws[4] = { Wss, Wvv, Wsv, Wvs };
#pragma unroll
        for (int m = 0; m < 4; m++)
#pragma unroll
            for (int kt = 0; kt < 4; kt++)
#pragma unroll
                for (int b2 = 0; b2 < 2; b2++) {
                    const int u = kt * 16 + (lane & 3) * 2 + b2 * 8;
                    const float w0 = __ldg(Ws[m] + u * 64 + wcol);
                    const float w1 = __ldg(Ws[m] + (u + 1) * 64 + wcol);
                    splitH2(w0, w1, Bh[m][kt][b2], Bl[m][kt][b2]);
                }
    }
    float2 bias2;
    {
        const int w0 = nw * 8 + (lane & 3) * 2;
        bias2 = make_float2(__ldg(bias + w0), __ldg(bias + w0 + 1));
    }

    const int nch = (n + RPC - 1) / RPC;
    int c = blockIdx.x;
    ChunkRegs cr;
    if (c < nch) {
        chunk_load(cr, in1, in2, c * RPC, n, t);
        chunk_store(smem, cr, t);
    }
    __syncthreads();

    int p = 0;
    for (; c < nch; c += gridDim.x) {
        const int cn = c + gridDim.x;
        const bool have_next = cn < nch;
        if (have_next) chunk_load(cr, in1, in2, cn * RPC, n, t);

        // ---- MMA phase on buffer p: warp computes M=16, N=8 (nw) ----
        float acc[6][4];
#pragma unroll
        for (int g = 0; g < 6; g++)
#pragma unroll
            for (int k = 0; k < 4; k++) acc[g][k] = 0.0f;

        const u32 abase = sbase + (u32)(p * BUF_BYTES);
        const int rr = lane & 15;
        const int rlo = rr & 7;
#pragma unroll
        for (int kt = 0; kt < 4; kt++) {
            const int cb = (kt * 2 + (lane >> 4)) ^ rlo;
            const u32 aoff = abase + (u32)(rr * 128 + cb * 16);

            u32 sA[4], bA[4], xA[4], yA[4], zA[4];
            ldsm4(sA, aoff + 0 * MAT_BYTES);
            ldsm4(bA, aoff + 1 * MAT_BYTES);
            ldsm4(xA, aoff + 2 * MAT_BYTES);
            ldsm4(yA, aoff + 3 * MAT_BYTES);
            ldsm4(zA, aoff + 4 * MAT_BYTES);

            // 12 MMAs, round-robin across 6 independent accumulators
            mma16816(acc[0], sA, Bh[0][kt]);
            mma16816(acc[1], bA, Bh[1][kt]);
            mma16816(acc[2], sA, Bh[2][kt]);
            mma16816(acc[3], xA, Bh[3][kt]);
            mma16816(acc[4], yA, Bh[3][kt]);
            mma16816(acc[5], zA, Bh[3][kt]);
            mma16816(acc[0], sA, Bl[0][kt]);
            mma16816(acc[1], bA, Bl[1][kt]);
            mma16816(acc[2], sA, Bl[2][kt]);
            mma16816(acc[3], xA, Bl[3][kt]);
            mma16816(acc[4], yA, Bl[3][kt]);
            mma16816(acc[5], zA, Bl[3][kt]);
        }

        // ---- epilogue ----
        const float4* sin2 = (const float4*)(smem + p * BUF_BYTES + NMAT * MAT_BYTES);
        const int row0 = c * RPC;
        const int wc = nw * 8 + (lane & 3) * 2;
#pragma unroll
        for (int h = 0; h < 2; h++) {
            const int rloc = (lane >> 2) + h * 8;
            const int row = row0 + rloc;
            if (row >= n) continue;
            const float4 q = sin2[rloc];
            float* o = out + (size_t)row * 256;
            const int ci = h * 2;
            const float s0  = q.x * acc[0][ci]     + acc[1][ci]     + bias2.x;
            const float s1v = q.x * acc[0][ci + 1] + acc[1][ci + 1] + bias2.y;
            *(float2*)(o + wc) = make_float2(s0, s1v);

            float vv6[6];
#pragma unroll
            for (int j = 0; j < 2; j++) {
                const float p3 = acc[2][ci + j];
                vv6[3 * j]     = p3 * q.y + acc[3][ci + j] * q.x;
                vv6[3 * j + 1] = p3 * q.z + acc[4][ci + j] * q.x;
                vv6[3 * j + 2] = p3 * q.w + acc[5][ci + j] * q.x;
            }
            float* ov = o + 64 + 3 * wc;
            *(float2*)(ov)     = make_float2(vv6[0], vv6[1]);
            *(float2*)(ov + 2) = make_float2(vv6[2], vv6[3]);
            *(float2*)(ov + 4) = make_float2(vv6[4], vv6[5]);
        }

        // ---- pack + store next chunk (loads have landed by now) ----
        if (have_next) chunk_store(smem + (p ^ 1) * BUF_BYTES, cr, t);

        __syncthreads();
        p ^= 1;
    }
}

extern "C" void kernel_launch(void* const* d_in, const int* in_sizes, int n_in,
                              void* d_out, int out_size)
{
    const float* in1  = (const float*)d_in[0];
    const float* in2  = (const float*)d_in[1];
    const float* Wss  = (const float*)d_in[2];
    const float* Wvv  = (const float*)d_in[3];
    const float* Wsv  = (const float*)d_in[4];
    const float* Wvs  = (const float*)d_in[5];
    const float* bias = (const float*)d_in[6];
    float* out = (float*)d_out;

    const int n = in_sizes[0] / 256;

    cudaFuncSetAttribute(o3tp_mma_kernel, cudaFuncAttributeMaxDynamicSharedMemorySize, SMEM_BYTES);

    int dev = 0, sms = 148;
    cudaGetDevice(&dev);
    cudaDeviceGetAttribute(&sms, cudaDevAttrMultiProcessorCount, dev);

    o3tp_mma_kernel<<<2 * sms, THREADS, SMEM_BYTES>>>(in1, in2, Wss, Wvv, Wsv, Wvs, bias, out, n);
}

// round 14
// speedup vs baseline: 1.4777x; 1.0089x over previous
#include <cuda_runtime.h>
#include <cuda_fp16.h>
#include <cstdint>
#include <cstddef>

// O3 tensor product, MUL=64, via mma.sync fp16 (A and B both fp16 hi-only,
// fp32 accum; error budget ~3.5e-4 << 1e-3 gate).
//   Q1 = s1 @ Wss ; Q2 = b @ Wvv ; P3 = s1 @ Wsv ; P4i = v1_i @ Wvs
//   out_s       = s2*Q1 + Q2 + bias
//   out_v[w][i] = P3[w]*v2_i + P4i[w]*s2
// (all reference scale factors cancel; b = dot(v1,v2)/sqrt(3))
//
// R12: 32-row chunks, 8 warps = 2 m-tiles x 4 n-slices(16 cols) -> A-fragment
// ldsm duplication drops 8x -> 4x (the measured L1 limiter); weights hi-only
// halves MMA count. 2 CTAs/SM for phase overlap.

#define THREADS 256
#define RPC 32                      // rows per chunk (two m16 tiles)
#define MAT_BYTES (RPC * 128)       // one staged A matrix: 32 rows x 128B
#define NMAT 5                      // s1, b, vx, vy, vz
#define BUF_BYTES (NMAT * MAT_BYTES + 512)
#define SMEM_BYTES (2 * BUF_BYTES)

typedef unsigned int u32;

__device__ __forceinline__ u32 smem_u32(const void* p) {
    u32 a; asm("{ .reg .u64 t; cvta.to.shared.u64 t, %1; cvt.u32.u64 %0, t; }" : "=r"(a) : "l"(p));
    return a;
}

__device__ __forceinline__ void ldsm4(u32* d, u32 addr) {
    asm volatile("ldmatrix.sync.aligned.m8n8.x4.shared.b16 {%0,%1,%2,%3}, [%4];"
                 : "=r"(d[0]), "=r"(d[1]), "=r"(d[2]), "=r"(d[3]) : "r"(addr));
}

__device__ __forceinline__ void mma16816(float* c, const u32* a, const u32* b) {
    asm volatile("mma.sync.aligned.m16n8k16.row.col.f32.f16.f16.f32 "
                 "{%0,%1,%2,%3},{%4,%5,%6,%7},{%8,%9},{%0,%1,%2,%3};"
                 : "+f"(c[0]), "+f"(c[1]), "+f"(c[2]), "+f"(c[3])
                 : "r"(a[0]), "r"(a[1]), "r"(a[2]), "r"(a[3]), "r"(b[0]), "r"(b[1]));
}

// pack 4 floats -> 4 fp16 (uint2), round-to-nearest
__device__ __forceinline__ uint2 pack4h(const float* x) {
    __half2 a = __floats2half2_rn(x[0], x[1]);
    __half2 b = __floats2half2_rn(x[2], x[3]);
    return make_uint2(*(u32*)&a, *(u32*)&b);
}

// Build one chunk: 512 work items (row r = i>>4, u-group g4 = i&15), 2 per thread.
// A-matrix order in staging: 0 s1, 1 b, 2 vx, 3 vy, 4 vz (fp16)
__device__ __forceinline__ void build_chunk(char* buf, const float* __restrict__ in1,
                                            const float* __restrict__ in2,
                                            int row0, int n, int t)
{
#pragma unroll
    for (int it = 0; it < 2; it++) {
        const int i = t + it * 256;
        const int r = i >> 4, g4 = i & 15;
        int row = row0 + r; if (row >= n) row = n - 1;
        const float4* p1 = (const float4*)(in1 + (size_t)row * 256);
        const float4 q = *(const float4*)(in2 + (size_t)row * 4);
        if (g4 == 0) *(float4*)(buf + NMAT * MAT_BYTES + r * 16) = q;

        const float4 s1a = p1[g4];
        const float4 v0 = p1[16 + 3 * g4];
        const float4 v1 = p1[16 + 3 * g4 + 1];
        const float4 v2 = p1[16 + 3 * g4 + 2];

        const float s1[4] = { s1a.x, s1a.y, s1a.z, s1a.w };
        const float vv[12] = { v0.x, v0.y, v0.z, v0.w, v1.x, v1.y, v1.z, v1.w,
                               v2.x, v2.y, v2.z, v2.w };
        const float INV_SQRT3 = 0.57735026918962576451f;
        float bb[4], vx[4], vy[4], vz[4];
#pragma unroll
        for (int j = 0; j < 4; j++) {
            vx[j] = vv[3 * j]; vy[j] = vv[3 * j + 1]; vz[j] = vv[3 * j + 2];
            bb[j] = (vx[j] * q.y + vy[j] * q.z + vz[j] * q.w) * INV_SQRT3;
        }

        // swizzled 8B offset: 16B block = g4>>1, XOR with row&7, sub-8B = g4&1
        const u32 off = (u32)(r * 128 + (((g4 >> 1) ^ (r & 7)) << 4) + (g4 & 1) * 8);
        *(uint2*)(buf + 0 * MAT_BYTES + off) = pack4h(s1);
        *(uint2*)(buf + 1 * MAT_BYTES + off) = pack4h(bb);
        *(uint2*)(buf + 2 * MAT_BYTES + off) = pack4h(vx);
        *(uint2*)(buf + 3 * MAT_BYTES + off) = pack4h(vy);
        *(uint2*)(buf + 4 * MAT_BYTES + off) = pack4h(vz);
    }
}

__global__ void __launch_bounds__(THREADS, 2)
o3tp_mma_kernel(const float* __restrict__ in1, const float* __restrict__ in2,
                const float* __restrict__ Wss, const float* __restrict__ Wvv,
                const float* __restrict__ Wsv, const float* __restrict__ Wvs,
                const float* __restrict__ bias, float* __restrict__ out, int n)
{
    extern __shared__ char smem[];
    const u32 sbase = smem_u32(smem);
    const int t = threadIdx.x, wid = t >> 5, lane = t & 31;
    const int mt = wid >> 2;        // m-tile: rows mt*16..mt*16+15
    const int ns = wid & 3;         // n-slice: cols ns*16..ns*16+15

    // ---- persistent B fragments: warp's 16-col slice of all 4 matrices,
    //      fp16 hi-only: B[mat][kt][ng][2] = 64 regs ----
    u32 B[4][4][2][2];
    {
        const float* Ws[4] = { Wss, Wvv, Wsv, Wvs };
#pragma unroll
        for (int m = 0; m < 4; m++)
#pragma unroll
            for (int kt = 0; kt < 4; kt++)
#pragma unroll
                for (int ng = 0; ng < 2; ng++) {
                    const int col = ns * 16 + ng * 8 + (lane >> 2);
#pragma unroll
                    for (int b2 = 0; b2 < 2; b2++) {
                        const int u = kt * 16 + (lane & 3) * 2 + b2 * 8;
                        const float w0 = __ldg(Ws[m] + u * 64 + col);
                        const float w1 = __ldg(Ws[m] + (u + 1) * 64 + col);
                        __half2 h = __floats2half2_rn(w0, w1);
                        B[m][kt][ng][b2] = *(u32*)&h;
                    }
                }
    }
    float2 bias2[2];
#pragma unroll
    for (int ng = 0; ng < 2; ng++) {
        const int w0 = ns * 16 + ng * 8 + (lane & 3) * 2;
        bias2[ng] = make_float2(__ldg(bias + w0), __ldg(bias + w0 + 1));
    }

    const int nch = (n + RPC - 1) / RPC;
    int c = blockIdx.x;
    if (c < nch) build_chunk(smem, in1, in2, c * RPC, n, t);
    __syncthreads();

    int p = 0;
    for (; c < nch; c += gridDim.x) {
        const int cn = c + gridDim.x;
        const bool have_next = cn < nch;

        // ---- MMA phase on buffer p: warp computes M=16 (mt), N=16 (ns) ----
        float acc[6][2][4];
#pragma unroll
        for (int g = 0; g < 6; g++)
#pragma unroll
            for (int ng = 0; ng < 2; ng++)
#pragma unroll
                for (int k = 0; k < 4; k++) acc[g][ng][k] = 0.0f;

        const u32 abase = sbase + (u32)(p * BUF_BYTES);
        const int rl = lane & 15;
        const int rlo = rl & 7;
        const int rr = mt * 16 + rl;
#pragma unroll
        for (int kt = 0; kt < 4; kt++) {
            const int cb = (kt * 2 + (lane >> 4)) ^ rlo;
            const u32 aoff = abase + (u32)(rr * 128 + cb * 16);

            u32 sA[4], bA[4], xA[4], yA[4], zA[4];
            ldsm4(sA, aoff + 0 * MAT_BYTES);
            ldsm4(bA, aoff + 1 * MAT_BYTES);
            ldsm4(xA, aoff + 2 * MAT_BYTES);
            ldsm4(yA, aoff + 3 * MAT_BYTES);
            ldsm4(zA, aoff + 4 * MAT_BYTES);

            // 12 MMAs: 6 products x 2 n-groups, round-robin across accumulators
#pragma unroll
            for (int ng = 0; ng < 2; ng++) {
                mma16816(acc[0][ng], sA, B[0][kt][ng]);
                mma16816(acc[1][ng], bA, B[1][kt][ng]);
                mma16816(acc[2][ng], sA, B[2][kt][ng]);
                mma16816(acc[3][ng], xA, B[3][kt][ng]);
                mma16816(acc[4][ng], yA, B[3][kt][ng]);
                mma16816(acc[5][ng], zA, B[3][kt][ng]);
            }
        }

        // ---- epilogue ----
        const float4* sin2 = (const float4*)(smem + p * BUF_BYTES + NMAT * MAT_BYTES);
        const int row0 = c * RPC;
#pragma unroll
        for (int h = 0; h < 2; h++) {
            const int rloc = mt * 16 + (lane >> 2) + h * 8;
            const int row = row0 + rloc;
            if (row >= n) continue;
            const float4 q = sin2[rloc];
            float* o = out + (size_t)row * 256;
            const int ci = h * 2;
#pragma unroll
            for (int ng = 0; ng < 2; ng++) {
                const int wc = ns * 16 + ng * 8 + (lane & 3) * 2;
                const float s0  = q.x * acc[0][ng][ci]     + acc[1][ng][ci]     + bias2[ng].x;
                const float s1v = q.x * acc[0][ng][ci + 1] + acc[1][ng][ci + 1] + bias2[ng].y;
                *(float2*)(o + wc) = make_float2(s0, s1v);

                float vv6[6];
#pragma unroll
                for (int j = 0; j < 2; j++) {
                    const float p3 = acc[2][ng][ci + j];
                    vv6[3 * j]     = p3 * q.y + acc[3][ng][ci + j] * q.x;
                    vv6[3 * j + 1] = p3 * q.z + acc[4][ng][ci + j] * q.x;
                    vv6[3 * j + 2] = p3 * q.w + acc[5][ng][ci + j] * q.x;
                }
                float* ov = o + 64 + 3 * wc;
                *(float2*)(ov)     = make_float2(vv6[0], vv6[1]);
                *(float2*)(ov + 2) = make_float2(vv6[2], vv6[3]);
                *(float2*)(ov + 4) = make_float2(vv6[4], vv6[5]);
            }
        }

        // ---- build next chunk (acc registers are dead here) ----
        if (have_next) build_chunk(smem + (p ^ 1) * BUF_BYTES, in1, in2, cn * RPC, n, t);

        __syncthreads();
        p ^= 1;
    }
}

extern "C" void kernel_launch(void* const* d_in, const int* in_sizes, int n_in,
                              void* d_out, int out_size)
{
    const float* in1  = (const float*)d_in[0];
    const float* in2  = (const float*)d_in[1];
    const float* Wss  = (const float*)d_in[2];
    const float* Wvv  = (const float*)d_in[3];
    const float* Wsv  = (const float*)d_in[4];
    const float* Wvs  = (const float*)d_in[5];
    const float* bias = (const float*)d_in[6];
    float* out = (float*)d_out;

    const int n = in_sizes[0] / 256;

    cudaFuncSetAttribute(o3tp_mma_kernel, cudaFuncAttributeMaxDynamicSharedMemorySize, SMEM_BYTES);

    int dev = 0, sms = 148;
    cudaGetDevice(&dev);
    cudaDeviceGetAttribute(&sms, cudaDevAttrMultiProcessorCount, dev);

    o3tp_mma_kernel<<<2 * sms, THREADS, SMEM_BYTES>>>(in1, in2, Wss, Wvv, Wsv, Wvs, bias, out, n);
}